// round 14
// baseline (speedup 1.0000x reference)
#include <cuda_runtime.h>
#include <math.h>

#define BB 16
#define HH 256
#define WW 256
#define CC 32
#define EM0 16
#define EM1 17
#define NROW 32

__device__ float2 g_A[(size_t)BB * EM1 * HH * CC];    // A[b,kw][h][ci]
__device__ float2 g_X[(size_t)NROW * EM1 * BB * CC];  // X[j,kw][b][ci]
__device__ float2 g_Z[(size_t)BB * HH * EM1 * CC];    // Z[row][kw][co]
__device__ float2 g_Wt[(size_t)NROW * EM1 * CC * CC]; // W[j,kw][ci][co]

#define MAKE_TW(sT)                                                     \
    for (int i = threadIdx.x; i < 256; i += 128) {                      \
        float s_, c_;                                                   \
        sincospif((float)i / 128.0f, &s_, &c_);                         \
        sT[i] = make_float2(c_, s_);                                    \
    }

// ---------------- K1: W-DFT 256 -> 17 bins, double fold ----------------
// blocks >= 4096 instead perform the weight transpose (fills g_Wt).
__global__ void __launch_bounds__(128) k1_wdft(const float* __restrict__ x,
                                               const float* __restrict__ w1r,
                                               const float* __restrict__ w1i,
                                               const float* __restrict__ w2r,
                                               const float* __restrict__ w2i) {
    if (blockIdx.x >= BB * HH) {
        int base = (blockIdx.x - BB * HH) * 256 + threadIdx.x;
#pragma unroll
        for (int rr = 0; rr < 2; rr++) {
            int t = base + rr * 128;
            if (t < CC * CC * EM0 * EM1) {
                int kw = t % EM1; int r = t / EM1;
                int hh = r & 15;  r >>= 4;
                int co = r & 31;  int ci = r >> 5;
                float a1r = __ldcs(&w1r[t]), a1i = __ldcs(&w1i[t]);
                float a2r = __ldcs(&w2r[t]), a2i = __ldcs(&w2i[t]);
                g_Wt[((size_t)(hh * EM1 + kw)) * 1024 + ci * 32 + co] = make_float2(a1r, a1i);
                g_Wt[((size_t)((hh + 16) * EM1 + kw)) * 1024 + ci * 32 + co] = make_float2(a2r, a2i);
            }
        }
        return;
    }
    __shared__ __align__(16) float sUE[64][32];
    __shared__ __align__(16) float sUO[64][32];
    __shared__ __align__(16) float sVE[64][32];
    __shared__ __align__(16) float sVO[64][32];
    __shared__ float2 sT[256];
    __shared__ float sRed[4][32];
    int row = blockIdx.x;
    int tid = threadIdx.x;
    MAKE_TW(sT)
    const float4* x4 = (const float4*)(x + (size_t)row * 8192);
    float4* UE4 = (float4*)sUE; float4* UO4 = (float4*)sUO;
    float4* VE4 = (float4*)sVE; float4* VO4 = (float4*)sVO;
#pragma unroll
    for (int it = 0; it < 4; it++) {
        int idx = tid + it * 128;
        int w = idx >> 3, cg = idx & 7;
        if (w == 0) {
            float4 a = __ldcs(&x4[64 * 8 + cg]);
            float4 b = __ldcs(&x4[192 * 8 + cg]);
            UE4[cg] = __ldcs(&x4[cg]);
            UO4[cg] = __ldcs(&x4[128 * 8 + cg]);
            VE4[cg] = make_float4(a.x + b.x, a.y + b.y, a.z + b.z, a.w + b.w);
            VO4[cg] = make_float4(a.x - b.x, a.y - b.y, a.z - b.z, a.w - b.w);
        } else {
            float4 a = __ldcs(&x4[w * 8 + cg]);
            float4 b = __ldcs(&x4[(256 - w) * 8 + cg]);
            float4 c = __ldcs(&x4[(128 - w) * 8 + cg]);
            float4 d = __ldcs(&x4[(128 + w) * 8 + cg]);
            UE4[w * 8 + cg] = make_float4(a.x + b.x + c.x + d.x, a.y + b.y + c.y + d.y,
                                          a.z + b.z + c.z + d.z, a.w + b.w + c.w + d.w);
            UO4[w * 8 + cg] = make_float4(a.x + b.x - c.x - d.x, a.y + b.y - c.y - d.y,
                                          a.z + b.z - c.z - d.z, a.w + b.w - c.w - d.w);
            VE4[w * 8 + cg] = make_float4(a.x - b.x + c.x - d.x, a.y - b.y + c.y - d.y,
                                          a.z - b.z + c.z - d.z, a.w - b.w + c.w - d.w);
            VO4[w * 8 + cg] = make_float4(a.x - b.x - c.x + d.x, a.y - b.y - c.y + d.y,
                                          a.z - b.z - c.z + d.z, a.w - b.w - c.w + d.w);
        }
    }
    __syncthreads();
    int lane = tid & 31, warp = tid >> 5;
    int cig = lane & 7, kwsub = lane >> 3;
    int k = warp * 4 + kwsub + 1;         // 1..16
    bool even = (k & 1) == 0;
    const float4* U = (even ? UE4 : UO4) + cig;
    const float4* V = (even ? VO4 : VE4) + cig;
    float R[4] = {0, 0, 0, 0}, I[4] = {0, 0, 0, 0};
    int tIdx = k;
#pragma unroll 7
    for (int w = 1; w < 64; w++) {
        float4 u = U[w * 8];
        float4 v = V[w * 8];
        float2 t = sT[tIdx];
        tIdx = (tIdx + k) & 255;
        R[0] += u.x * t.x; R[1] += u.y * t.x; R[2] += u.z * t.x; R[3] += u.w * t.x;
        I[0] -= v.x * t.y; I[1] -= v.y * t.y; I[2] -= v.z * t.y; I[3] -= v.w * t.y;
    }
    const float S = 1.0f / 65536.0f;
    int ci0 = cig * 4;
    int b = row >> 8, h = row & 255;
    {
        float sgn = ((k >> 1) & 1) ? -1.0f : 1.0f;
        float2 o[4];
#pragma unroll
        for (int c = 0; c < 4; c++) {
            float x0 = sUE[0][ci0 + c], x128 = sUO[0][ci0 + c];
            float u64 = sVE[0][ci0 + c], v64 = sVO[0][ci0 + c];
            float re, im;
            if (even) { re = R[c] + x0 + x128 + sgn * u64; im = I[c]; }
            else      { re = R[c] + x0 - x128;             im = I[c] - sgn * v64; }
            o[c] = make_float2(re * S, im * S);
        }
        float4* dst = (float4*)(g_A + (((size_t)(b * EM1 + k)) * HH + h) * CC + ci0);
        dst[0] = make_float4(o[0].x, o[0].y, o[1].x, o[1].y);
        dst[1] = make_float4(o[2].x, o[2].y, o[3].x, o[3].y);
    }
    // kw = 0
    {
        int c = tid & 31, grp = tid >> 5;
        float acc = 0.f;
#pragma unroll 4
        for (int w = grp * 16; w < grp * 16 + 16; w++) acc += sUE[w][c];
        sRed[grp][c] = acc;
        __syncthreads();
        if (tid < 32) {
            float r = (sRed[0][tid] + sRed[1][tid] + sRed[2][tid] + sRed[3][tid]
                       + sUO[0][tid] + sVE[0][tid]) * S;
            g_A[(((size_t)(b * EM1 + 0)) * HH + h) * CC + tid] = make_float2(r, 0.f);
        }
    }
}

// ---------------- K2: H-DFT (double-folded, 64 iters), half-split ----------------
__global__ void __launch_bounds__(128) k2_hdft() {
    __shared__ __align__(16) float2 sUE[64 * 16];
    __shared__ __align__(16) float2 sUO[64 * 16];
    __shared__ __align__(16) float2 sVE[64 * 16];
    __shared__ __align__(16) float2 sVO[64 * 16];
    __shared__ float2 sT[256];
    __shared__ float2 sRedC[8][16];
    int blk = blockIdx.x;
    int half = blk & 1; int bk = blk >> 1;
    int b = bk / EM1, kw = bk % EM1;
    int tid = threadIdx.x;
    const float2* A = g_A + ((size_t)(b * EM1 + kw)) * (HH * CC) + half * 16;
    MAKE_TW(sT)
#pragma unroll
    for (int it = 0; it < 8; it++) {
        int i = tid + it * 128;
        int h = i >> 4, c = i & 15;
        if (h == 0) {
            float2 a64 = __ldcs(&A[64 * CC + c]), a192 = __ldcs(&A[192 * CC + c]);
            sUE[c] = __ldcs(&A[c]);
            sUO[c] = __ldcs(&A[128 * CC + c]);
            sVE[c] = make_float2(a64.x + a192.x, a64.y + a192.y);
            sVO[c] = make_float2(a64.x - a192.x, a64.y - a192.y);
        } else {
            float2 a = __ldcs(&A[h * CC + c]);
            float2 b2 = __ldcs(&A[(256 - h) * CC + c]);
            float2 cc = __ldcs(&A[(128 - h) * CC + c]);
            float2 d = __ldcs(&A[(128 + h) * CC + c]);
            sUE[i] = make_float2(a.x + b2.x + cc.x + d.x, a.y + b2.y + cc.y + d.y);
            sUO[i] = make_float2(a.x + b2.x - cc.x - d.x, a.y + b2.y - cc.y - d.y);
            sVE[i] = make_float2(a.x - b2.x + cc.x - d.x, a.y - b2.y + cc.y - d.y);
            sVO[i] = make_float2(a.x - b2.x - cc.x + d.x, a.y - b2.y - cc.y + d.y);
        }
    }
    __syncthreads();
    int cig = tid & 7, fg = tid >> 3;
    int c0 = cig * 2;
    int f = fg + 1;                      // 1..16
    bool even = (f & 1) == 0;
    const float2* Uc = (even ? sUE : sUO) + c0;
    const float2* Vs = (even ? sVO : sVE) + c0;
    float Cr0 = 0, Ci0 = 0, Cr1 = 0, Ci1 = 0;
    float Sr0 = 0, Si0 = 0, Sr1 = 0, Si1 = 0;
    int ti = f;
#pragma unroll 7
    for (int h = 1; h < 64; h++) {
        float2 t = sT[ti];
        ti = (ti + f) & 255;
        float4 u = *(const float4*)&Uc[h * 16];
        float4 v = *(const float4*)&Vs[h * 16];
        Cr0 += u.x * t.x; Ci0 += u.y * t.x; Cr1 += u.z * t.x; Ci1 += u.w * t.x;
        Sr0 += v.x * t.y; Si0 += v.y * t.y; Sr1 += v.z * t.y; Si1 += v.w * t.y;
    }
    {
        float sgn = ((f >> 1) & 1) ? -1.0f : 1.0f;
        float2 a0a = sUE[c0], a0b = sUE[c0 + 1];
        float2 a1a = sUO[c0], a1b = sUO[c0 + 1];
        if (even) {
            float2 u64a = sVE[c0], u64b = sVE[c0 + 1];
            Cr0 += a0a.x + a1a.x + sgn * u64a.x; Ci0 += a0a.y + a1a.y + sgn * u64a.y;
            Cr1 += a0b.x + a1b.x + sgn * u64b.x; Ci1 += a0b.y + a1b.y + sgn * u64b.y;
        } else {
            float2 v64a = sVO[c0], v64b = sVO[c0 + 1];
            Cr0 += a0a.x - a1a.x; Ci0 += a0a.y - a1a.y;
            Cr1 += a0b.x - a1b.x; Ci1 += a0b.y - a1b.y;
            Sr0 += sgn * v64a.x; Si0 += sgn * v64a.y;
            Sr1 += sgn * v64b.x; Si1 += sgn * v64b.y;
        }
    }
    size_t obase = (size_t)kw * BB + b;
    if (f <= 15) {   // j = f : X = C - iS
        float4* dst = (float4*)(g_X + ((size_t)f * EM1 * BB + obase) * CC + half * 16 + c0);
        dst[0] = make_float4(Cr0 + Si0, Ci0 - Sr0, Cr1 + Si1, Ci1 - Sr1);
    }
    {                // j = 32 - f : X = C + iS
        int j = 32 - f;
        float4* dst = (float4*)(g_X + ((size_t)j * EM1 * BB + obase) * CC + half * 16 + c0);
        dst[0] = make_float4(Cr0 - Si0, Ci0 + Sr0, Cr1 - Si1, Ci1 + Sr1);
    }
    // f = 0 (j = 0)
    {
        int cc = tid & 15, grp = tid >> 4;
        float2 acc = make_float2(0.f, 0.f);
#pragma unroll 4
        for (int h = grp * 8; h < grp * 8 + 8; h++) {
            float2 u = sUE[h * 16 + cc];
            acc.x += u.x; acc.y += u.y;
        }
        sRedC[grp][cc] = acc;
        __syncthreads();
        if (tid < 16) {
            float2 s = sUO[tid];                       // a128
            float2 u64 = sVE[tid];
            s.x += u64.x; s.y += u64.y;
#pragma unroll
            for (int g = 0; g < 8; g++) { s.x += sRedC[g][tid].x; s.y += sRedC[g][tid].y; }
            g_X[((size_t)0 * EM1 * BB + obase) * CC + half * 16 + tid] = s;
        }
    }
}

// ---------------- K34: channel mix + H-inverse fused, half-split ----------------
__global__ void __launch_bounds__(128) k34_mixhinv() {
    __shared__ __align__(16) float2 sX[NROW * CC];    // [j][ci] 8KB
    __shared__ __align__(16) float2 sY[NROW * 16];    // [j][col] 4KB
    __shared__ __align__(16) float2 sP[EM1 * 16];
    __shared__ __align__(16) float2 sQ[EM1 * 16];
    __shared__ float2 sT[256];
    int blk = blockIdx.x;
    int half = blk & 1; int bk = blk >> 1;
    int b = bk / EM1, kw = bk % EM1;
    int tid = threadIdx.x;
    MAKE_TW(sT)
    // load X[j][ci]: per j a contiguous 256B run
    {
        float4* sX4 = (float4*)sX;
        for (int i = tid; i < NROW * 16; i += 128) {
            int j = i >> 4, q = i & 15;
            const float4* src = (const float4*)(g_X + ((size_t)(j * EM1 + kw) * BB + b) * CC);
            sX4[i] = __ldcs(&src[q]);
        }
    }
    __syncthreads();
    // mix: thread owns coq = (tid&7)*2 (2 co), jg = tid>>3; j = jg + 16m
    {
        int coq = (tid & 7) * 2, jg = tid >> 3;
#pragma unroll
        for (int m = 0; m < 2; m++) {
            int j = jg + 16 * m;
            const float4* wrow = (const float4*)(g_Wt + ((size_t)(j * EM1 + kw)) * 1024
                                                 + half * 16 + coq);
            const float2* xrow = sX + j * CC;
            float r0 = 0.f, i0 = 0.f, r1 = 0.f, i1 = 0.f;
#pragma unroll 8
            for (int ci = 0; ci < 32; ci++) {
                float4 wv = __ldg(&wrow[ci * 16]);     // row stride 32 float2
                float2 xv = xrow[ci];
                r0 += xv.x * wv.x - xv.y * wv.y;
                i0 += xv.x * wv.y + xv.y * wv.x;
                r1 += xv.x * wv.z - xv.y * wv.w;
                i1 += xv.x * wv.w + xv.y * wv.z;
            }
            *(float4*)&sY[j * 16 + coq] = make_float4(r0, i0, r1, i1);
        }
    }
    __syncthreads();
    // fold Y -> P/Q
    for (int i = tid; i < EM1 * 16; i += 128) {
        int f = i >> 4, c = i & 15;
        float2 p, q;
        if (f == 0) { p = sY[c]; q = make_float2(0.f, 0.f); }
        else if (f == 16) {
            float2 yb = sY[16 * 16 + c];
            p = yb; q = make_float2(-yb.x, -yb.y);
        } else {
            float2 ya = sY[f * 16 + c], yb = sY[(32 - f) * 16 + c];
            p = make_float2(ya.x + yb.x, ya.y + yb.y);
            q = make_float2(ya.x - yb.x, ya.y - yb.y);
        }
        sP[i] = p; sQ[i] = q;
    }
    __syncthreads();
    int cig = tid & 3, hg = tid >> 2;     // hg 0..31
    int c0 = cig * 4;
    float EcR[2][4], EcI[2][4], OcR[2][4], OcI[2][4];
    float EsR[2][4], EsI[2][4], OsR[2][4], OsI[2][4];
    int hx[2];
#pragma unroll
    for (int m = 0; m < 2; m++) {
        hx[m] = 1 + hg + 32 * m;
#pragma unroll
        for (int c = 0; c < 4; c++) {
            EcR[m][c]=0; EcI[m][c]=0; OcR[m][c]=0; OcI[m][c]=0;
            EsR[m][c]=0; EsI[m][c]=0; OsR[m][c]=0; OsI[m][c]=0;
        }
    }
    int ti0 = 0, ti1 = 0;
#pragma unroll
    for (int f = 0; f < 17; f++) {
        float4 p01 = *(const float4*)&sP[f * 16 + c0];
        float4 p23 = *(const float4*)&sP[f * 16 + c0 + 2];
        float4 q01 = *(const float4*)&sQ[f * 16 + c0];
        float4 q23 = *(const float4*)&sQ[f * 16 + c0 + 2];
        float2 t0 = sT[ti0]; ti0 = (ti0 + hx[0]) & 255;
        float2 t1 = sT[ti1]; ti1 = (ti1 + hx[1]) & 255;
        if ((f & 1) == 0) {
            EcR[0][0] += p01.x*t0.x; EcI[0][0] += p01.y*t0.x; EsR[0][0] += q01.x*t0.y; EsI[0][0] += q01.y*t0.y;
            EcR[0][1] += p01.z*t0.x; EcI[0][1] += p01.w*t0.x; EsR[0][1] += q01.z*t0.y; EsI[0][1] += q01.w*t0.y;
            EcR[0][2] += p23.x*t0.x; EcI[0][2] += p23.y*t0.x; EsR[0][2] += q23.x*t0.y; EsI[0][2] += q23.y*t0.y;
            EcR[0][3] += p23.z*t0.x; EcI[0][3] += p23.w*t0.x; EsR[0][3] += q23.z*t0.y; EsI[0][3] += q23.w*t0.y;
            EcR[1][0] += p01.x*t1.x; EcI[1][0] += p01.y*t1.x; EsR[1][0] += q01.x*t1.y; EsI[1][0] += q01.y*t1.y;
            EcR[1][1] += p01.z*t1.x; EcI[1][1] += p01.w*t1.x; EsR[1][1] += q01.z*t1.y; EsI[1][1] += q01.w*t1.y;
            EcR[1][2] += p23.x*t1.x; EcI[1][2] += p23.y*t1.x; EsR[1][2] += q23.x*t1.y; EsI[1][2] += q23.y*t1.y;
            EcR[1][3] += p23.z*t1.x; EcI[1][3] += p23.w*t1.x; EsR[1][3] += q23.z*t1.y; EsI[1][3] += q23.w*t1.y;
        } else {
            OcR[0][0] += p01.x*t0.x; OcI[0][0] += p01.y*t0.x; OsR[0][0] += q01.x*t0.y; OsI[0][0] += q01.y*t0.y;
            OcR[0][1] += p01.z*t0.x; OcI[0][1] += p01.w*t0.x; OsR[0][1] += q01.z*t0.y; OsI[0][1] += q01.w*t0.y;
            OcR[0][2] += p23.x*t0.x; OcI[0][2] += p23.y*t0.x; OsR[0][2] += q23.x*t0.y; OsI[0][2] += q23.y*t0.y;
            OcR[0][3] += p23.z*t0.x; OcI[0][3] += p23.w*t0.x; OsR[0][3] += q23.z*t0.y; OsI[0][3] += q23.w*t0.y;
            OcR[1][0] += p01.x*t1.x; OcI[1][0] += p01.y*t1.x; OsR[1][0] += q01.x*t1.y; OsI[1][0] += q01.y*t1.y;
            OcR[1][1] += p01.z*t1.x; OcI[1][1] += p01.w*t1.x; OsR[1][1] += q01.z*t1.y; OsI[1][1] += q01.w*t1.y;
            OcR[1][2] += p23.x*t1.x; OcI[1][2] += p23.y*t1.x; OsR[1][2] += q23.x*t1.y; OsI[1][2] += q23.y*t1.y;
            OcR[1][3] += p23.z*t1.x; OcI[1][3] += p23.w*t1.x; OsR[1][3] += q23.z*t1.y; OsI[1][3] += q23.w*t1.y;
        }
    }
    int gc0 = half * 16 + c0;
#pragma unroll
    for (int m = 0; m < 2; m++) {
        int h = hx[m];
        float E1r[4], E1i[4], O1r[4], O1i[4], E2r[4], E2i[4], O2r[4], O2i[4];
#pragma unroll
        for (int c = 0; c < 4; c++) {
            E1r[c] = EcR[m][c] + OcR[m][c]; E1i[c] = EcI[m][c] + OcI[m][c];
            O1r[c] = EsR[m][c] + OsR[m][c]; O1i[c] = EsI[m][c] + OsI[m][c];
            E2r[c] = EcR[m][c] - OcR[m][c]; E2i[c] = EcI[m][c] - OcI[m][c];
            O2r[c] = -EsR[m][c] + OsR[m][c]; O2i[c] = -EsI[m][c] + OsI[m][c];
        }
        {
            int row = b * 256 + h;
            float4* d = (float4*)(g_Z + ((size_t)row * EM1 + kw) * CC + gc0);
            d[0] = make_float4(E1r[0]-O1i[0], E1i[0]+O1r[0], E1r[1]-O1i[1], E1i[1]+O1r[1]);
            d[1] = make_float4(E1r[2]-O1i[2], E1i[2]+O1r[2], E1r[3]-O1i[3], E1i[3]+O1r[3]);
            int row2 = b * 256 + (256 - h);
            float4* d2 = (float4*)(g_Z + ((size_t)row2 * EM1 + kw) * CC + gc0);
            d2[0] = make_float4(E1r[0]+O1i[0], E1i[0]-O1r[0], E1r[1]+O1i[1], E1i[1]-O1r[1]);
            d2[1] = make_float4(E1r[2]+O1i[2], E1i[2]-O1r[2], E1r[3]+O1i[3], E1i[3]-O1r[3]);
        }
        if (h != 64) {
            int row = b * 256 + (128 - h);
            float4* d = (float4*)(g_Z + ((size_t)row * EM1 + kw) * CC + gc0);
            d[0] = make_float4(E2r[0]-O2i[0], E2i[0]+O2r[0], E2r[1]-O2i[1], E2i[1]+O2r[1]);
            d[1] = make_float4(E2r[2]-O2i[2], E2i[2]+O2r[2], E2r[3]-O2i[3], E2i[3]+O2r[3]);
            int row2 = b * 256 + (128 + h);
            float4* d2 = (float4*)(g_Z + ((size_t)row2 * EM1 + kw) * CC + gc0);
            d2[0] = make_float4(E2r[0]+O2i[0], E2i[0]-O2r[0], E2r[1]+O2i[1], E2i[1]-O2r[1]);
            d2[1] = make_float4(E2r[2]+O2i[2], E2i[2]-O2r[2], E2r[3]+O2i[3], E2i[3]-O2r[3]);
        }
    }
    // h = 0 and h = 128
    if (tid < 32) {
        int c = tid & 15;
        bool is128 = tid >= 16;
        float2 acc = make_float2(0.f, 0.f);
#pragma unroll
        for (int f = 0; f < 17; f++) {
            float2 p = sP[f * 16 + c];
            float s = (is128 && (f & 1)) ? -1.0f : 1.0f;
            acc.x += s * p.x; acc.y += s * p.y;
        }
        int row = b * 256 + (is128 ? 128 : 0);
        g_Z[((size_t)row * EM1 + kw) * CC + half * 16 + c] = acc;
    }
}

// ---------------- K5: W-inverse (parity fold) + bias, 256 threads ----------------
__global__ void __launch_bounds__(256) k5_winv(const float* __restrict__ bias,
                                               float* __restrict__ out) {
    __shared__ __align__(16) float2 sZ[EM1 * 32];
    __shared__ float2 sT[256];
    __shared__ float sB[32];
    int row = blockIdx.x;
    int tid = threadIdx.x;
    const float4* src = (const float4*)(g_Z + (size_t)row * EM1 * CC);
    float4* sZ4 = (float4*)sZ;
    for (int i = tid; i < 272; i += 256) sZ4[i] = __ldcs(&src[i]);
    {
        float s_, c_;
        sincospif((float)tid / 128.0f, &s_, &c_);
        sT[tid] = make_float2(c_, s_);
    }
    if (tid < 32) sB[tid] = bias[tid];
    __syncthreads();
    int cig = tid & 7, wg = tid >> 3;     // wg 0..31
    int c0 = cig * 4;
    float base[4];
#pragma unroll
    for (int c = 0; c < 4; c++) base[c] = sZ[c0 + c].x + sB[c0 + c];
    float* orow = out + (size_t)row * 8192;
    float Pe[2][4], Po[2][4], Qe[2][4], Qo[2][4];
    int wv[2], idx[2];
#pragma unroll
    for (int m = 0; m < 2; m++) {
        wv[m] = 1 + wg + 32 * m;          // 1..64
        idx[m] = wv[m];
#pragma unroll
        for (int c = 0; c < 4; c++) { Pe[m][c]=0; Po[m][c]=0; Qe[m][c]=0; Qo[m][c]=0; }
    }
#pragma unroll
    for (int k = 1; k <= 16; k++) {
        float4 z01 = *(const float4*)&sZ[k * 32 + c0];
        float4 z23 = *(const float4*)&sZ[k * 32 + c0 + 2];
#pragma unroll
        for (int m = 0; m < 2; m++) {
            float2 t = sT[idx[m]];
            idx[m] = (idx[m] + wv[m]) & 255;
            if ((k & 1) == 0) {
                Pe[m][0] += z01.x * t.x; Qe[m][0] += z01.y * t.y;
                Pe[m][1] += z01.z * t.x; Qe[m][1] += z01.w * t.y;
                Pe[m][2] += z23.x * t.x; Qe[m][2] += z23.y * t.y;
                Pe[m][3] += z23.z * t.x; Qe[m][3] += z23.w * t.y;
            } else {
                Po[m][0] += z01.x * t.x; Qo[m][0] += z01.y * t.y;
                Po[m][1] += z01.z * t.x; Qo[m][1] += z01.w * t.y;
                Po[m][2] += z23.x * t.x; Qo[m][2] += z23.y * t.y;
                Po[m][3] += z23.z * t.x; Qo[m][3] += z23.w * t.y;
            }
        }
    }
#pragma unroll
    for (int m = 0; m < 2; m++) {
        int w = wv[m];
        float4 o1, o2;
        o1 = make_float4(base[0] + 2.0f*(Pe[m][0]+Po[m][0]-Qe[m][0]-Qo[m][0]),
                         base[1] + 2.0f*(Pe[m][1]+Po[m][1]-Qe[m][1]-Qo[m][1]),
                         base[2] + 2.0f*(Pe[m][2]+Po[m][2]-Qe[m][2]-Qo[m][2]),
                         base[3] + 2.0f*(Pe[m][3]+Po[m][3]-Qe[m][3]-Qo[m][3]));
        o2 = make_float4(base[0] + 2.0f*(Pe[m][0]+Po[m][0]+Qe[m][0]+Qo[m][0]),
                         base[1] + 2.0f*(Pe[m][1]+Po[m][1]+Qe[m][1]+Qo[m][1]),
                         base[2] + 2.0f*(Pe[m][2]+Po[m][2]+Qe[m][2]+Qo[m][2]),
                         base[3] + 2.0f*(Pe[m][3]+Po[m][3]+Qe[m][3]+Qo[m][3]));
        __stcs((float4*)(orow + w * 32 + c0), o1);
        __stcs((float4*)(orow + (256 - w) * 32 + c0), o2);
        if (w != 64) {
            float4 o3, o4;
            o3 = make_float4(base[0] + 2.0f*(Pe[m][0]-Po[m][0]+Qe[m][0]-Qo[m][0]),
                             base[1] + 2.0f*(Pe[m][1]-Po[m][1]+Qe[m][1]-Qo[m][1]),
                             base[2] + 2.0f*(Pe[m][2]-Po[m][2]+Qe[m][2]-Qo[m][2]),
                             base[3] + 2.0f*(Pe[m][3]-Po[m][3]+Qe[m][3]-Qo[m][3]));
            o4 = make_float4(base[0] + 2.0f*(Pe[m][0]-Po[m][0]-Qe[m][0]+Qo[m][0]),
                             base[1] + 2.0f*(Pe[m][1]-Po[m][1]-Qe[m][1]+Qo[m][1]),
                             base[2] + 2.0f*(Pe[m][2]-Po[m][2]-Qe[m][2]+Qo[m][2]),
                             base[3] + 2.0f*(Pe[m][3]-Po[m][3]-Qe[m][3]+Qo[m][3]));
            __stcs((float4*)(orow + (128 - w) * 32 + c0), o3);
            __stcs((float4*)(orow + (128 + w) * 32 + c0), o4);
        }
    }
    // w = 0 and w = 128
    if (tid < 64) {
        int c = tid & 31;
        bool is128 = tid >= 32;
        float acc = 0.f;
#pragma unroll
        for (int k = 1; k <= 16; k++) {
            float zr = sZ[k * 32 + c].x;
            acc += (is128 && (k & 1)) ? -zr : zr;
        }
        __stcs(&orow[(is128 ? 128 * 32 : 0) + c], sZ[c].x + sB[c] + 2.0f * acc);
    }
}

extern "C" void kernel_launch(void* const* d_in, const int* in_sizes, int n_in,
                              void* d_out, int out_size) {
    const float* x    = (const float*)d_in[0];
    const float* w1r  = (const float*)d_in[1];
    const float* w1i  = (const float*)d_in[2];
    const float* w2r  = (const float*)d_in[3];
    const float* w2i  = (const float*)d_in[4];
    const float* bias = (const float*)d_in[5];
    float* out = (float*)d_out;

    k1_wdft<<<BB * HH + 1088, 128>>>(x, w1r, w1i, w2r, w2i);
    k2_hdft<<<BB * EM1 * 2, 128>>>();
    k34_mixhinv<<<BB * EM1 * 2, 128>>>();
    k5_winv<<<BB * HH, 256>>>(bias, out);
}

// round 15
// speedup vs baseline: 1.0922x; 1.0922x over previous
#include <cuda_runtime.h>
#include <math.h>

#define BB 16
#define HH 256
#define WW 256
#define CC 32
#define EM0 16
#define EM1 17
#define NROW 32

__device__ float2 g_A[(size_t)BB * EM1 * HH * CC];    // A[b,kw][h][ci]
__device__ float2 g_X[(size_t)NROW * EM1 * BB * CC];  // X[j,kw][b][ci]
__device__ float2 g_Z[(size_t)BB * HH * EM1 * CC];    // Z[row][kw][co]
__device__ float2 g_Wt[(size_t)NROW * EM1 * CC * CC]; // W[j,kw][ci][co]

#define MAKE_TW(sT)                                                     \
    for (int i = threadIdx.x; i < 256; i += 128) {                      \
        float s_, c_;                                                   \
        sincospif((float)i / 128.0f, &s_, &c_);                         \
        sT[i] = make_float2(c_, s_);                                    \
    }

// ---------------- K1: W-DFT 256 -> 17 bins, double fold ----------------
// blocks >= 4096 instead perform the weight transpose (fills g_Wt).
__global__ void __launch_bounds__(128) k1_wdft(const float* __restrict__ x,
                                               const float* __restrict__ w1r,
                                               const float* __restrict__ w1i,
                                               const float* __restrict__ w2r,
                                               const float* __restrict__ w2i) {
    if (blockIdx.x >= BB * HH) {
        int base = (blockIdx.x - BB * HH) * 256 + threadIdx.x;
#pragma unroll
        for (int rr = 0; rr < 2; rr++) {
            int t = base + rr * 128;
            if (t < CC * CC * EM0 * EM1) {
                int kw = t % EM1; int r = t / EM1;
                int hh = r & 15;  r >>= 4;
                int co = r & 31;  int ci = r >> 5;
                float a1r = __ldcs(&w1r[t]), a1i = __ldcs(&w1i[t]);
                float a2r = __ldcs(&w2r[t]), a2i = __ldcs(&w2i[t]);
                g_Wt[((size_t)(hh * EM1 + kw)) * 1024 + ci * 32 + co] = make_float2(a1r, a1i);
                g_Wt[((size_t)((hh + 16) * EM1 + kw)) * 1024 + ci * 32 + co] = make_float2(a2r, a2i);
            }
        }
        return;
    }
    __shared__ __align__(16) float sUE[64][32];
    __shared__ __align__(16) float sUO[64][32];
    __shared__ __align__(16) float sVE[64][32];
    __shared__ __align__(16) float sVO[64][32];
    __shared__ float2 sT[256];
    __shared__ float sRed[4][32];
    int row = blockIdx.x;
    int tid = threadIdx.x;
    MAKE_TW(sT)
    const float4* x4 = (const float4*)(x + (size_t)row * 8192);
    float4* UE4 = (float4*)sUE; float4* UO4 = (float4*)sUO;
    float4* VE4 = (float4*)sVE; float4* VO4 = (float4*)sVO;
#pragma unroll
    for (int it = 0; it < 4; it++) {
        int idx = tid + it * 128;
        int w = idx >> 3, cg = idx & 7;
        if (w == 0) {
            float4 a = __ldcs(&x4[64 * 8 + cg]);
            float4 b = __ldcs(&x4[192 * 8 + cg]);
            UE4[cg] = __ldcs(&x4[cg]);
            UO4[cg] = __ldcs(&x4[128 * 8 + cg]);
            VE4[cg] = make_float4(a.x + b.x, a.y + b.y, a.z + b.z, a.w + b.w);
            VO4[cg] = make_float4(a.x - b.x, a.y - b.y, a.z - b.z, a.w - b.w);
        } else {
            float4 a = __ldcs(&x4[w * 8 + cg]);
            float4 b = __ldcs(&x4[(256 - w) * 8 + cg]);
            float4 c = __ldcs(&x4[(128 - w) * 8 + cg]);
            float4 d = __ldcs(&x4[(128 + w) * 8 + cg]);
            UE4[w * 8 + cg] = make_float4(a.x + b.x + c.x + d.x, a.y + b.y + c.y + d.y,
                                          a.z + b.z + c.z + d.z, a.w + b.w + c.w + d.w);
            UO4[w * 8 + cg] = make_float4(a.x + b.x - c.x - d.x, a.y + b.y - c.y - d.y,
                                          a.z + b.z - c.z - d.z, a.w + b.w - c.w - d.w);
            VE4[w * 8 + cg] = make_float4(a.x - b.x + c.x - d.x, a.y - b.y + c.y - d.y,
                                          a.z - b.z + c.z - d.z, a.w - b.w + c.w - d.w);
            VO4[w * 8 + cg] = make_float4(a.x - b.x - c.x + d.x, a.y - b.y - c.y + d.y,
                                          a.z - b.z - c.z + d.z, a.w - b.w - c.w + d.w);
        }
    }
    __syncthreads();
    int lane = tid & 31, warp = tid >> 5;
    int cig = lane & 7, kwsub = lane >> 3;
    int k = warp * 4 + kwsub + 1;         // 1..16
    bool even = (k & 1) == 0;
    const float4* U = (even ? UE4 : UO4) + cig;
    const float4* V = (even ? VO4 : VE4) + cig;
    float R[4] = {0, 0, 0, 0}, I[4] = {0, 0, 0, 0};
    int tIdx = k;
#pragma unroll 7
    for (int w = 1; w < 64; w++) {
        float4 u = U[w * 8];
        float4 v = V[w * 8];
        float2 t = sT[tIdx];
        tIdx = (tIdx + k) & 255;
        R[0] += u.x * t.x; R[1] += u.y * t.x; R[2] += u.z * t.x; R[3] += u.w * t.x;
        I[0] -= v.x * t.y; I[1] -= v.y * t.y; I[2] -= v.z * t.y; I[3] -= v.w * t.y;
    }
    const float S = 1.0f / 65536.0f;
    int ci0 = cig * 4;
    int b = row >> 8, h = row & 255;
    {
        float sgn = ((k >> 1) & 1) ? -1.0f : 1.0f;
        float2 o[4];
#pragma unroll
        for (int c = 0; c < 4; c++) {
            float x0 = sUE[0][ci0 + c], x128 = sUO[0][ci0 + c];
            float u64 = sVE[0][ci0 + c], v64 = sVO[0][ci0 + c];
            float re, im;
            if (even) { re = R[c] + x0 + x128 + sgn * u64; im = I[c]; }
            else      { re = R[c] + x0 - x128;             im = I[c] - sgn * v64; }
            o[c] = make_float2(re * S, im * S);
        }
        float4* dst = (float4*)(g_A + (((size_t)(b * EM1 + k)) * HH + h) * CC + ci0);
        dst[0] = make_float4(o[0].x, o[0].y, o[1].x, o[1].y);
        dst[1] = make_float4(o[2].x, o[2].y, o[3].x, o[3].y);
    }
    // kw = 0
    {
        int c = tid & 31, grp = tid >> 5;
        float acc = 0.f;
#pragma unroll 4
        for (int w = grp * 16; w < grp * 16 + 16; w++) acc += sUE[w][c];
        sRed[grp][c] = acc;
        __syncthreads();
        if (tid < 32) {
            float r = (sRed[0][tid] + sRed[1][tid] + sRed[2][tid] + sRed[3][tid]
                       + sUO[0][tid] + sVE[0][tid]) * S;
            g_A[(((size_t)(b * EM1 + 0)) * HH + h) * CC + tid] = make_float2(r, 0.f);
        }
    }
}

// ---------------- K2: H-DFT (double-folded, 64 iters), half-split ----------------
__global__ void __launch_bounds__(128) k2_hdft() {
    __shared__ __align__(16) float2 sUE[64 * 16];
    __shared__ __align__(16) float2 sUO[64 * 16];
    __shared__ __align__(16) float2 sVE[64 * 16];
    __shared__ __align__(16) float2 sVO[64 * 16];
    __shared__ float2 sT[256];
    __shared__ float2 sRedC[8][16];
    int blk = blockIdx.x;
    int half = blk & 1; int bk = blk >> 1;
    int b = bk / EM1, kw = bk % EM1;
    int tid = threadIdx.x;
    const float2* A = g_A + ((size_t)(b * EM1 + kw)) * (HH * CC) + half * 16;
    MAKE_TW(sT)
#pragma unroll
    for (int it = 0; it < 8; it++) {
        int i = tid + it * 128;
        int h = i >> 4, c = i & 15;
        if (h == 0) {
            float2 a64 = __ldcs(&A[64 * CC + c]), a192 = __ldcs(&A[192 * CC + c]);
            sUE[c] = __ldcs(&A[c]);
            sUO[c] = __ldcs(&A[128 * CC + c]);
            sVE[c] = make_float2(a64.x + a192.x, a64.y + a192.y);
            sVO[c] = make_float2(a64.x - a192.x, a64.y - a192.y);
        } else {
            float2 a = __ldcs(&A[h * CC + c]);
            float2 b2 = __ldcs(&A[(256 - h) * CC + c]);
            float2 cc = __ldcs(&A[(128 - h) * CC + c]);
            float2 d = __ldcs(&A[(128 + h) * CC + c]);
            sUE[i] = make_float2(a.x + b2.x + cc.x + d.x, a.y + b2.y + cc.y + d.y);
            sUO[i] = make_float2(a.x + b2.x - cc.x - d.x, a.y + b2.y - cc.y - d.y);
            sVE[i] = make_float2(a.x - b2.x + cc.x - d.x, a.y - b2.y + cc.y - d.y);
            sVO[i] = make_float2(a.x - b2.x - cc.x + d.x, a.y - b2.y - cc.y + d.y);
        }
    }
    __syncthreads();
    int cig = tid & 7, fg = tid >> 3;
    int c0 = cig * 2;
    int f = fg + 1;                      // 1..16
    bool even = (f & 1) == 0;
    const float2* Uc = (even ? sUE : sUO) + c0;
    const float2* Vs = (even ? sVO : sVE) + c0;
    float Cr0 = 0, Ci0 = 0, Cr1 = 0, Ci1 = 0;
    float Sr0 = 0, Si0 = 0, Sr1 = 0, Si1 = 0;
    int ti = f;
#pragma unroll 7
    for (int h = 1; h < 64; h++) {
        float2 t = sT[ti];
        ti = (ti + f) & 255;
        float4 u = *(const float4*)&Uc[h * 16];
        float4 v = *(const float4*)&Vs[h * 16];
        Cr0 += u.x * t.x; Ci0 += u.y * t.x; Cr1 += u.z * t.x; Ci1 += u.w * t.x;
        Sr0 += v.x * t.y; Si0 += v.y * t.y; Sr1 += v.z * t.y; Si1 += v.w * t.y;
    }
    {
        float sgn = ((f >> 1) & 1) ? -1.0f : 1.0f;
        float2 a0a = sUE[c0], a0b = sUE[c0 + 1];
        float2 a1a = sUO[c0], a1b = sUO[c0 + 1];
        if (even) {
            float2 u64a = sVE[c0], u64b = sVE[c0 + 1];
            Cr0 += a0a.x + a1a.x + sgn * u64a.x; Ci0 += a0a.y + a1a.y + sgn * u64a.y;
            Cr1 += a0b.x + a1b.x + sgn * u64b.x; Ci1 += a0b.y + a1b.y + sgn * u64b.y;
        } else {
            float2 v64a = sVO[c0], v64b = sVO[c0 + 1];
            Cr0 += a0a.x - a1a.x; Ci0 += a0a.y - a1a.y;
            Cr1 += a0b.x - a1b.x; Ci1 += a0b.y - a1b.y;
            Sr0 += sgn * v64a.x; Si0 += sgn * v64a.y;
            Sr1 += sgn * v64b.x; Si1 += sgn * v64b.y;
        }
    }
    size_t obase = (size_t)kw * BB + b;
    if (f <= 15) {   // j = f : X = C - iS
        float4* dst = (float4*)(g_X + ((size_t)f * EM1 * BB + obase) * CC + half * 16 + c0);
        dst[0] = make_float4(Cr0 + Si0, Ci0 - Sr0, Cr1 + Si1, Ci1 - Sr1);
    }
    {                // j = 32 - f : X = C + iS
        int j = 32 - f;
        float4* dst = (float4*)(g_X + ((size_t)j * EM1 * BB + obase) * CC + half * 16 + c0);
        dst[0] = make_float4(Cr0 - Si0, Ci0 + Sr0, Cr1 - Si1, Ci1 + Sr1);
    }
    // f = 0 (j = 0)
    {
        int cc = tid & 15, grp = tid >> 4;
        float2 acc = make_float2(0.f, 0.f);
#pragma unroll 4
        for (int h = grp * 8; h < grp * 8 + 8; h++) {
            float2 u = sUE[h * 16 + cc];
            acc.x += u.x; acc.y += u.y;
        }
        sRedC[grp][cc] = acc;
        __syncthreads();
        if (tid < 16) {
            float2 s = sUO[tid];                       // a128
            float2 u64 = sVE[tid];
            s.x += u64.x; s.y += u64.y;
#pragma unroll
            for (int g = 0; g < 8; g++) { s.x += sRedC[g][tid].x; s.y += sRedC[g][tid].y; }
            g_X[((size_t)0 * EM1 * BB + obase) * CC + half * 16 + tid] = s;
        }
    }
}

// ---------------- K34: channel mix + H-inverse fused, half-split ----------------
__global__ void __launch_bounds__(128) k34_mixhinv() {
    __shared__ __align__(16) float2 sX[NROW * CC];    // [j][ci] 8KB
    __shared__ __align__(16) float2 sY[NROW * 16];    // [j][col] 4KB
    __shared__ __align__(16) float2 sP[EM1 * 16];
    __shared__ __align__(16) float2 sQ[EM1 * 16];
    __shared__ float2 sT[256];
    int blk = blockIdx.x;
    int half = blk & 1; int bk = blk >> 1;
    int b = bk / EM1, kw = bk % EM1;
    int tid = threadIdx.x;
    MAKE_TW(sT)
    // load X[j][ci]: per j a contiguous 256B run
    {
        float4* sX4 = (float4*)sX;
        for (int i = tid; i < NROW * 16; i += 128) {
            int j = i >> 4, q = i & 15;
            const float4* src = (const float4*)(g_X + ((size_t)(j * EM1 + kw) * BB + b) * CC);
            sX4[i] = __ldcs(&src[q]);
        }
    }
    __syncthreads();
    // mix: thread owns coq = (tid&7)*2 (2 co), jg = tid>>3; j = jg + 16m
    {
        int coq = (tid & 7) * 2, jg = tid >> 3;
#pragma unroll
        for (int m = 0; m < 2; m++) {
            int j = jg + 16 * m;
            const float4* wrow = (const float4*)(g_Wt + ((size_t)(j * EM1 + kw)) * 1024
                                                 + half * 16 + coq);
            const float2* xrow = sX + j * CC;
            float r0 = 0.f, i0 = 0.f, r1 = 0.f, i1 = 0.f;
#pragma unroll 8
            for (int ci = 0; ci < 32; ci++) {
                float4 wv = __ldg(&wrow[ci * 16]);     // row stride 32 float2
                float2 xv = xrow[ci];
                r0 += xv.x * wv.x - xv.y * wv.y;
                i0 += xv.x * wv.y + xv.y * wv.x;
                r1 += xv.x * wv.z - xv.y * wv.w;
                i1 += xv.x * wv.w + xv.y * wv.z;
            }
            *(float4*)&sY[j * 16 + coq] = make_float4(r0, i0, r1, i1);
        }
    }
    __syncthreads();
    // fold Y -> P/Q
    for (int i = tid; i < EM1 * 16; i += 128) {
        int f = i >> 4, c = i & 15;
        float2 p, q;
        if (f == 0) { p = sY[c]; q = make_float2(0.f, 0.f); }
        else if (f == 16) {
            float2 yb = sY[16 * 16 + c];
            p = yb; q = make_float2(-yb.x, -yb.y);
        } else {
            float2 ya = sY[f * 16 + c], yb = sY[(32 - f) * 16 + c];
            p = make_float2(ya.x + yb.x, ya.y + yb.y);
            q = make_float2(ya.x - yb.x, ya.y - yb.y);
        }
        sP[i] = p; sQ[i] = q;
    }
    __syncthreads();
    int cig = tid & 3, hg = tid >> 2;     // hg 0..31
    int c0 = cig * 4;
    float EcR[2][4], EcI[2][4], OcR[2][4], OcI[2][4];
    float EsR[2][4], EsI[2][4], OsR[2][4], OsI[2][4];
    int hx[2];
#pragma unroll
    for (int m = 0; m < 2; m++) {
        hx[m] = 1 + hg + 32 * m;
#pragma unroll
        for (int c = 0; c < 4; c++) {
            EcR[m][c]=0; EcI[m][c]=0; OcR[m][c]=0; OcI[m][c]=0;
            EsR[m][c]=0; EsI[m][c]=0; OsR[m][c]=0; OsI[m][c]=0;
        }
    }
    int ti0 = 0, ti1 = 0;
#pragma unroll
    for (int f = 0; f < 17; f++) {
        float4 p01 = *(const float4*)&sP[f * 16 + c0];
        float4 p23 = *(const float4*)&sP[f * 16 + c0 + 2];
        float4 q01 = *(const float4*)&sQ[f * 16 + c0];
        float4 q23 = *(const float4*)&sQ[f * 16 + c0 + 2];
        float2 t0 = sT[ti0]; ti0 = (ti0 + hx[0]) & 255;
        float2 t1 = sT[ti1]; ti1 = (ti1 + hx[1]) & 255;
        if ((f & 1) == 0) {
            EcR[0][0] += p01.x*t0.x; EcI[0][0] += p01.y*t0.x; EsR[0][0] += q01.x*t0.y; EsI[0][0] += q01.y*t0.y;
            EcR[0][1] += p01.z*t0.x; EcI[0][1] += p01.w*t0.x; EsR[0][1] += q01.z*t0.y; EsI[0][1] += q01.w*t0.y;
            EcR[0][2] += p23.x*t0.x; EcI[0][2] += p23.y*t0.x; EsR[0][2] += q23.x*t0.y; EsI[0][2] += q23.y*t0.y;
            EcR[0][3] += p23.z*t0.x; EcI[0][3] += p23.w*t0.x; EsR[0][3] += q23.z*t0.y; EsI[0][3] += q23.w*t0.y;
            EcR[1][0] += p01.x*t1.x; EcI[1][0] += p01.y*t1.x; EsR[1][0] += q01.x*t1.y; EsI[1][0] += q01.y*t1.y;
            EcR[1][1] += p01.z*t1.x; EcI[1][1] += p01.w*t1.x; EsR[1][1] += q01.z*t1.y; EsI[1][1] += q01.w*t1.y;
            EcR[1][2] += p23.x*t1.x; EcI[1][2] += p23.y*t1.x; EsR[1][2] += q23.x*t1.y; EsI[1][2] += q23.y*t1.y;
            EcR[1][3] += p23.z*t1.x; EcI[1][3] += p23.w*t1.x; EsR[1][3] += q23.z*t1.y; EsI[1][3] += q23.w*t1.y;
        } else {
            OcR[0][0] += p01.x*t0.x; OcI[0][0] += p01.y*t0.x; OsR[0][0] += q01.x*t0.y; OsI[0][0] += q01.y*t0.y;
            OcR[0][1] += p01.z*t0.x; OcI[0][1] += p01.w*t0.x; OsR[0][1] += q01.z*t0.y; OsI[0][1] += q01.w*t0.y;
            OcR[0][2] += p23.x*t0.x; OcI[0][2] += p23.y*t0.x; OsR[0][2] += q23.x*t0.y; OsI[0][2] += q23.y*t0.y;
            OcR[0][3] += p23.z*t0.x; OcI[0][3] += p23.w*t0.x; OsR[0][3] += q23.z*t0.y; OsI[0][3] += q23.w*t0.y;
            OcR[1][0] += p01.x*t1.x; OcI[1][0] += p01.y*t1.x; OsR[1][0] += q01.x*t1.y; OsI[1][0] += q01.y*t1.y;
            OcR[1][1] += p01.z*t1.x; OcI[1][1] += p01.w*t1.x; OsR[1][1] += q01.z*t1.y; OsI[1][1] += q01.w*t1.y;
            OcR[1][2] += p23.x*t1.x; OcI[1][2] += p23.y*t1.x; OsR[1][2] += q23.x*t1.y; OsI[1][2] += q23.y*t1.y;
            OcR[1][3] += p23.z*t1.x; OcI[1][3] += p23.w*t1.x; OsR[1][3] += q23.z*t1.y; OsI[1][3] += q23.w*t1.y;
        }
    }
    int gc0 = half * 16 + c0;
#pragma unroll
    for (int m = 0; m < 2; m++) {
        int h = hx[m];
        float E1r[4], E1i[4], O1r[4], O1i[4], E2r[4], E2i[4], O2r[4], O2i[4];
#pragma unroll
        for (int c = 0; c < 4; c++) {
            E1r[c] = EcR[m][c] + OcR[m][c]; E1i[c] = EcI[m][c] + OcI[m][c];
            O1r[c] = EsR[m][c] + OsR[m][c]; O1i[c] = EsI[m][c] + OsI[m][c];
            E2r[c] = EcR[m][c] - OcR[m][c]; E2i[c] = EcI[m][c] - OcI[m][c];
            O2r[c] = -EsR[m][c] + OsR[m][c]; O2i[c] = -EsI[m][c] + OsI[m][c];
        }
        {
            int row = b * 256 + h;
            float4* d = (float4*)(g_Z + ((size_t)row * EM1 + kw) * CC + gc0);
            d[0] = make_float4(E1r[0]-O1i[0], E1i[0]+O1r[0], E1r[1]-O1i[1], E1i[1]+O1r[1]);
            d[1] = make_float4(E1r[2]-O1i[2], E1i[2]+O1r[2], E1r[3]-O1i[3], E1i[3]+O1r[3]);
            int row2 = b * 256 + (256 - h);
            float4* d2 = (float4*)(g_Z + ((size_t)row2 * EM1 + kw) * CC + gc0);
            d2[0] = make_float4(E1r[0]+O1i[0], E1i[0]-O1r[0], E1r[1]+O1i[1], E1i[1]-O1r[1]);
            d2[1] = make_float4(E1r[2]+O1i[2], E1i[2]-O1r[2], E1r[3]+O1i[3], E1i[3]-O1r[3]);
        }
        if (h != 64) {
            int row = b * 256 + (128 - h);
            float4* d = (float4*)(g_Z + ((size_t)row * EM1 + kw) * CC + gc0);
            d[0] = make_float4(E2r[0]-O2i[0], E2i[0]+O2r[0], E2r[1]-O2i[1], E2i[1]+O2r[1]);
            d[1] = make_float4(E2r[2]-O2i[2], E2i[2]+O2r[2], E2r[3]-O2i[3], E2i[3]+O2r[3]);
            int row2 = b * 256 + (128 + h);
            float4* d2 = (float4*)(g_Z + ((size_t)row2 * EM1 + kw) * CC + gc0);
            d2[0] = make_float4(E2r[0]+O2i[0], E2i[0]-O2r[0], E2r[1]+O2i[1], E2i[1]-O2r[1]);
            d2[1] = make_float4(E2r[2]+O2i[2], E2i[2]-O2r[2], E2r[3]+O2i[3], E2i[3]-O2r[3]);
        }
    }
    // h = 0 and h = 128
    if (tid < 32) {
        int c = tid & 15;
        bool is128 = tid >= 16;
        float2 acc = make_float2(0.f, 0.f);
#pragma unroll
        for (int f = 0; f < 17; f++) {
            float2 p = sP[f * 16 + c];
            float s = (is128 && (f & 1)) ? -1.0f : 1.0f;
            acc.x += s * p.x; acc.y += s * p.y;
        }
        int row = b * 256 + (is128 ? 128 : 0);
        g_Z[((size_t)row * EM1 + kw) * CC + half * 16 + c] = acc;
    }
}

// ---------------- K5: W-inverse (parity fold, twiddle recurrence) + bias ----------------
__global__ void __launch_bounds__(128) k5_winv(const float* __restrict__ bias,
                                               float* __restrict__ out) {
    __shared__ __align__(16) float2 sZ[EM1 * 32];
    __shared__ float sB[32];
    int row = blockIdx.x;
    int tid = threadIdx.x;
    const float4* src = (const float4*)(g_Z + (size_t)row * EM1 * CC);
    float4* sZ4 = (float4*)sZ;
    for (int i = tid; i < 272; i += 128) sZ4[i] = __ldcs(&src[i]);
    if (tid < 32) sB[tid] = bias[tid];
    __syncthreads();
    int cig = tid & 7, wg = tid >> 3;     // wg 0..15
    int c0 = cig * 4;
    float base[4];
#pragma unroll
    for (int c = 0; c < 4; c++) base[c] = sZ[c0 + c].x + sB[c0 + c];
    float* orow = out + (size_t)row * 8192;
    float Pe[4][4], Po[4][4], Qe[4][4], Qo[4][4];
    int wv[4];
    float tr[4], ti_[4], sr[4], si[4];    // rotation state + step (angle 2*pi*w/256)
#pragma unroll
    for (int m = 0; m < 4; m++) {
        wv[m] = 1 + wg + 16 * m;          // 1..64
        float s_, c_;
        sincospif((float)wv[m] / 128.0f, &s_, &c_);
        sr[m] = c_; si[m] = s_;           // step
        tr[m] = c_; ti_[m] = s_;          // t at k = 1
#pragma unroll
        for (int c = 0; c < 4; c++) { Pe[m][c]=0; Po[m][c]=0; Qe[m][c]=0; Qo[m][c]=0; }
    }
#pragma unroll
    for (int k = 1; k <= 16; k++) {
        float4 z01 = *(const float4*)&sZ[k * 32 + c0];
        float4 z23 = *(const float4*)&sZ[k * 32 + c0 + 2];
#pragma unroll
        for (int m = 0; m < 4; m++) {
            float tx = tr[m], ty = ti_[m];
            // advance rotation: t *= step
            tr[m] = tx * sr[m] - ty * si[m];
            ti_[m] = tx * si[m] + ty * sr[m];
            if ((k & 1) == 0) {
                Pe[m][0] += z01.x * tx; Qe[m][0] += z01.y * ty;
                Pe[m][1] += z01.z * tx; Qe[m][1] += z01.w * ty;
                Pe[m][2] += z23.x * tx; Qe[m][2] += z23.y * ty;
                Pe[m][3] += z23.z * tx; Qe[m][3] += z23.w * ty;
            } else {
                Po[m][0] += z01.x * tx; Qo[m][0] += z01.y * ty;
                Po[m][1] += z01.z * tx; Qo[m][1] += z01.w * ty;
                Po[m][2] += z23.x * tx; Qo[m][2] += z23.y * ty;
                Po[m][3] += z23.z * tx; Qo[m][3] += z23.w * ty;
            }
        }
    }
#pragma unroll
    for (int m = 0; m < 4; m++) {
        int w = wv[m];
        float4 o1, o2;
        o1 = make_float4(base[0] + 2.0f*(Pe[m][0]+Po[m][0]-Qe[m][0]-Qo[m][0]),
                         base[1] + 2.0f*(Pe[m][1]+Po[m][1]-Qe[m][1]-Qo[m][1]),
                         base[2] + 2.0f*(Pe[m][2]+Po[m][2]-Qe[m][2]-Qo[m][2]),
                         base[3] + 2.0f*(Pe[m][3]+Po[m][3]-Qe[m][3]-Qo[m][3]));
        o2 = make_float4(base[0] + 2.0f*(Pe[m][0]+Po[m][0]+Qe[m][0]+Qo[m][0]),
                         base[1] + 2.0f*(Pe[m][1]+Po[m][1]+Qe[m][1]+Qo[m][1]),
                         base[2] + 2.0f*(Pe[m][2]+Po[m][2]+Qe[m][2]+Qo[m][2]),
                         base[3] + 2.0f*(Pe[m][3]+Po[m][3]+Qe[m][3]+Qo[m][3]));
        __stcs((float4*)(orow + w * 32 + c0), o1);
        __stcs((float4*)(orow + (256 - w) * 32 + c0), o2);
        if (w != 64) {
            float4 o3, o4;
            o3 = make_float4(base[0] + 2.0f*(Pe[m][0]-Po[m][0]+Qe[m][0]-Qo[m][0]),
                             base[1] + 2.0f*(Pe[m][1]-Po[m][1]+Qe[m][1]-Qo[m][1]),
                             base[2] + 2.0f*(Pe[m][2]-Po[m][2]+Qe[m][2]-Qo[m][2]),
                             base[3] + 2.0f*(Pe[m][3]-Po[m][3]+Qe[m][3]-Qo[m][3]));
            o4 = make_float4(base[0] + 2.0f*(Pe[m][0]-Po[m][0]-Qe[m][0]+Qo[m][0]),
                             base[1] + 2.0f*(Pe[m][1]-Po[m][1]-Qe[m][1]+Qo[m][1]),
                             base[2] + 2.0f*(Pe[m][2]-Po[m][2]-Qe[m][2]+Qo[m][2]),
                             base[3] + 2.0f*(Pe[m][3]-Po[m][3]-Qe[m][3]+Qo[m][3]));
            __stcs((float4*)(orow + (128 - w) * 32 + c0), o3);
            __stcs((float4*)(orow + (128 + w) * 32 + c0), o4);
        }
    }
    // w = 0 and w = 128
    if (tid < 64) {
        int c = tid & 31;
        bool is128 = tid >= 32;
        float acc = 0.f;
#pragma unroll
        for (int k = 1; k <= 16; k++) {
            float zr = sZ[k * 32 + c].x;
            acc += (is128 && (k & 1)) ? -zr : zr;
        }
        __stcs(&orow[(is128 ? 128 * 32 : 0) + c], sZ[c].x + sB[c] + 2.0f * acc);
    }
}

extern "C" void kernel_launch(void* const* d_in, const int* in_sizes, int n_in,
                              void* d_out, int out_size) {
    const float* x    = (const float*)d_in[0];
    const float* w1r  = (const float*)d_in[1];
    const float* w1i  = (const float*)d_in[2];
    const float* w2r  = (const float*)d_in[3];
    const float* w2i  = (const float*)d_in[4];
    const float* bias = (const float*)d_in[5];
    float* out = (float*)d_out;

    k1_wdft<<<BB * HH + 1088, 128>>>(x, w1r, w1i, w2r, w2i);
    k2_hdft<<<BB * EM1 * 2, 128>>>();
    k34_mixhinv<<<BB * EM1 * 2, 128>>>();
    k5_winv<<<BB * HH, 128>>>(bias, out);
}

// round 17
// speedup vs baseline: 1.0963x; 1.0038x over previous
#include <cuda_runtime.h>
#include <math.h>

#define BB 16
#define HH 256
#define WW 256
#define CC 32
#define EM0 16
#define EM1 17
#define NROW 32

__device__ float2 g_A[(size_t)BB * EM1 * HH * CC];    // A[b,kw][h][ci]
__device__ float2 g_Z[(size_t)BB * HH * EM1 * CC];    // Z[row][kw][co]
__device__ float2 g_Wt[(size_t)NROW * EM1 * CC * CC]; // W[j,kw][ci][co]

#define MAKE_TW(sT)                                                     \
    for (int i = threadIdx.x; i < 256; i += 128) {                      \
        float s_, c_;                                                   \
        sincospif((float)i / 128.0f, &s_, &c_);                         \
        sT[i] = make_float2(c_, s_);                                    \
    }

// ---------------- K1: W-DFT 256 -> 17 bins, double fold ----------------
// blocks >= 4096 instead perform the weight transpose (fills g_Wt).
__global__ void __launch_bounds__(128) k1_wdft(const float* __restrict__ x,
                                               const float* __restrict__ w1r,
                                               const float* __restrict__ w1i,
                                               const float* __restrict__ w2r,
                                               const float* __restrict__ w2i) {
    if (blockIdx.x >= BB * HH) {
        int base = (blockIdx.x - BB * HH) * 256 + threadIdx.x;
#pragma unroll
        for (int rr = 0; rr < 2; rr++) {
            int t = base + rr * 128;
            if (t < CC * CC * EM0 * EM1) {
                int kw = t % EM1; int r = t / EM1;
                int hh = r & 15;  r >>= 4;
                int co = r & 31;  int ci = r >> 5;
                float a1r = __ldcs(&w1r[t]), a1i = __ldcs(&w1i[t]);
                float a2r = __ldcs(&w2r[t]), a2i = __ldcs(&w2i[t]);
                g_Wt[((size_t)(hh * EM1 + kw)) * 1024 + ci * 32 + co] = make_float2(a1r, a1i);
                g_Wt[((size_t)((hh + 16) * EM1 + kw)) * 1024 + ci * 32 + co] = make_float2(a2r, a2i);
            }
        }
        return;
    }
    __shared__ __align__(16) float sUE[64][32];
    __shared__ __align__(16) float sUO[64][32];
    __shared__ __align__(16) float sVE[64][32];
    __shared__ __align__(16) float sVO[64][32];
    __shared__ float2 sT[256];
    __shared__ float sRed[4][32];
    int row = blockIdx.x;
    int tid = threadIdx.x;
    MAKE_TW(sT)
    const float4* x4 = (const float4*)(x + (size_t)row * 8192);
    float4* UE4 = (float4*)sUE; float4* UO4 = (float4*)sUO;
    float4* VE4 = (float4*)sVE; float4* VO4 = (float4*)sVO;
#pragma unroll
    for (int it = 0; it < 4; it++) {
        int idx = tid + it * 128;
        int w = idx >> 3, cg = idx & 7;
        if (w == 0) {
            float4 a = __ldcs(&x4[64 * 8 + cg]);
            float4 b = __ldcs(&x4[192 * 8 + cg]);
            UE4[cg] = __ldcs(&x4[cg]);
            UO4[cg] = __ldcs(&x4[128 * 8 + cg]);
            VE4[cg] = make_float4(a.x + b.x, a.y + b.y, a.z + b.z, a.w + b.w);
            VO4[cg] = make_float4(a.x - b.x, a.y - b.y, a.z - b.z, a.w - b.w);
        } else {
            float4 a = __ldcs(&x4[w * 8 + cg]);
            float4 b = __ldcs(&x4[(256 - w) * 8 + cg]);
            float4 c = __ldcs(&x4[(128 - w) * 8 + cg]);
            float4 d = __ldcs(&x4[(128 + w) * 8 + cg]);
            UE4[w * 8 + cg] = make_float4(a.x + b.x + c.x + d.x, a.y + b.y + c.y + d.y,
                                          a.z + b.z + c.z + d.z, a.w + b.w + c.w + d.w);
            UO4[w * 8 + cg] = make_float4(a.x + b.x - c.x - d.x, a.y + b.y - c.y - d.y,
                                          a.z + b.z - c.z - d.z, a.w + b.w - c.w - d.w);
            VE4[w * 8 + cg] = make_float4(a.x - b.x + c.x - d.x, a.y - b.y + c.y - d.y,
                                          a.z - b.z + c.z - d.z, a.w - b.w + c.w - d.w);
            VO4[w * 8 + cg] = make_float4(a.x - b.x - c.x + d.x, a.y - b.y - c.y + d.y,
                                          a.z - b.z - c.z + d.z, a.w - b.w - c.w + d.w);
        }
    }
    __syncthreads();
    int lane = tid & 31, warp = tid >> 5;
    int cig = lane & 7, kwsub = lane >> 3;
    int k = warp * 4 + kwsub + 1;         // 1..16
    bool even = (k & 1) == 0;
    const float4* U = (even ? UE4 : UO4) + cig;
    const float4* V = (even ? VO4 : VE4) + cig;
    float R[4] = {0, 0, 0, 0}, I[4] = {0, 0, 0, 0};
    int tIdx = k;
#pragma unroll 7
    for (int w = 1; w < 64; w++) {
        float4 u = U[w * 8];
        float4 v = V[w * 8];
        float2 t = sT[tIdx];
        tIdx = (tIdx + k) & 255;
        R[0] += u.x * t.x; R[1] += u.y * t.x; R[2] += u.z * t.x; R[3] += u.w * t.x;
        I[0] -= v.x * t.y; I[1] -= v.y * t.y; I[2] -= v.z * t.y; I[3] -= v.w * t.y;
    }
    const float S = 1.0f / 65536.0f;
    int ci0 = cig * 4;
    int b = row >> 8, h = row & 255;
    {
        float sgn = ((k >> 1) & 1) ? -1.0f : 1.0f;
        float2 o[4];
#pragma unroll
        for (int c = 0; c < 4; c++) {
            float x0 = sUE[0][ci0 + c], x128 = sUO[0][ci0 + c];
            float u64 = sVE[0][ci0 + c], v64 = sVO[0][ci0 + c];
            float re, im;
            if (even) { re = R[c] + x0 + x128 + sgn * u64; im = I[c]; }
            else      { re = R[c] + x0 - x128;             im = I[c] - sgn * v64; }
            o[c] = make_float2(re * S, im * S);
        }
        float4* dst = (float4*)(g_A + (((size_t)(b * EM1 + k)) * HH + h) * CC + ci0);
        dst[0] = make_float4(o[0].x, o[0].y, o[1].x, o[1].y);
        dst[1] = make_float4(o[2].x, o[2].y, o[3].x, o[3].y);
    }
    // kw = 0
    {
        int c = tid & 31, grp = tid >> 5;
        float acc = 0.f;
#pragma unroll 4
        for (int w = grp * 16; w < grp * 16 + 16; w++) acc += sUE[w][c];
        sRed[grp][c] = acc;
        __syncthreads();
        if (tid < 32) {
            float r = (sRed[0][tid] + sRed[1][tid] + sRed[2][tid] + sRed[3][tid]
                       + sUO[0][tid] + sVE[0][tid]) * S;
            g_A[(((size_t)(b * EM1 + 0)) * HH + h) * CC + tid] = make_float2(r, 0.f);
        }
    }
}

// ---------------- K234: H-DFT + channel mix + H-inverse, fully fused ----------------
// block = (b, kw), 256 threads, dynamic smem.
// smem layout (float2 units):
//   sUE 0, sUO 2048, sVE 4096, sVO 6144   (64 h x 32 ci each)
//   sX 8192 (32 j x 32 ci), sY 9216 (32 j x 32 co)
//   sP 10240, sQ 10784 (17 x 32), sT 11328 (256), sRed 11584 (8 x 32) ; total 11840
extern __shared__ float2 dsm[];
__global__ void __launch_bounds__(256) k234() {
    float2* sUE = dsm;
    float2* sUO = dsm + 2048;
    float2* sVE = dsm + 4096;
    float2* sVO = dsm + 6144;
    float2* sX  = dsm + 8192;
    float2* sY  = dsm + 9216;
    float2* sP  = dsm + 10240;
    float2* sQ  = dsm + 10784;
    float2* sT  = dsm + 11328;
    float2* sRd = dsm + 11584;
    int blk = blockIdx.x;
    int b = blk / EM1, kw = blk % EM1;
    int tid = threadIdx.x;
    {
        float s_, c_;
        sincospif((float)tid / 128.0f, &s_, &c_);
        sT[tid] = make_float2(c_, s_);
    }
    const float2* A = g_A + ((size_t)(b * EM1 + kw)) * (HH * CC);
    // -------- phase A load + radix-2^2 fold --------
#pragma unroll
    for (int it = 0; it < 8; it++) {
        int i = tid + it * 256;
        int h = i >> 5, c = i & 31;
        if (h == 0) {
            float2 a64 = __ldcs(&A[64 * CC + c]), a192 = __ldcs(&A[192 * CC + c]);
            sUE[c] = __ldcs(&A[c]);
            sUO[c] = __ldcs(&A[128 * CC + c]);
            sVE[c] = make_float2(a64.x + a192.x, a64.y + a192.y);
            sVO[c] = make_float2(a64.x - a192.x, a64.y - a192.y);
        } else {
            float2 a = __ldcs(&A[h * CC + c]);
            float2 b2 = __ldcs(&A[(256 - h) * CC + c]);
            float2 cc = __ldcs(&A[(128 - h) * CC + c]);
            float2 d = __ldcs(&A[(128 + h) * CC + c]);
            sUE[i] = make_float2(a.x + b2.x + cc.x + d.x, a.y + b2.y + cc.y + d.y);
            sUO[i] = make_float2(a.x + b2.x - cc.x - d.x, a.y + b2.y - cc.y - d.y);
            sVE[i] = make_float2(a.x - b2.x + cc.x - d.x, a.y - b2.y + cc.y - d.y);
            sVO[i] = make_float2(a.x - b2.x - cc.x + d.x, a.y - b2.y - cc.y + d.y);
        }
    }
    __syncthreads();
    // -------- phase A DFT: thread = (f 1..16, ch-pair 0..15) --------
    {
        int cp = tid & 15, fg = tid >> 4;
        int c0 = cp * 2;
        int f = fg + 1;
        bool even = (f & 1) == 0;
        const float2* Uc = (even ? sUE : sUO) + c0;
        const float2* Vs = (even ? sVO : sVE) + c0;
        float Cr0 = 0, Ci0 = 0, Cr1 = 0, Ci1 = 0;
        float Sr0 = 0, Si0 = 0, Sr1 = 0, Si1 = 0;
        int ti = f;
#pragma unroll 7
        for (int h = 1; h < 64; h++) {
            float2 t = sT[ti];
            ti = (ti + f) & 255;
            float4 u = *(const float4*)&Uc[h * 32];
            float4 v = *(const float4*)&Vs[h * 32];
            Cr0 += u.x * t.x; Ci0 += u.y * t.x; Cr1 += u.z * t.x; Ci1 += u.w * t.x;
            Sr0 += v.x * t.y; Si0 += v.y * t.y; Sr1 += v.z * t.y; Si1 += v.w * t.y;
        }
        {
            float sgn = ((f >> 1) & 1) ? -1.0f : 1.0f;
            float2 a0a = sUE[c0], a0b = sUE[c0 + 1];
            float2 a1a = sUO[c0], a1b = sUO[c0 + 1];
            if (even) {
                float2 u64a = sVE[c0], u64b = sVE[c0 + 1];
                Cr0 += a0a.x + a1a.x + sgn * u64a.x; Ci0 += a0a.y + a1a.y + sgn * u64a.y;
                Cr1 += a0b.x + a1b.x + sgn * u64b.x; Ci1 += a0b.y + a1b.y + sgn * u64b.y;
            } else {
                float2 v64a = sVO[c0], v64b = sVO[c0 + 1];
                Cr0 += a0a.x - a1a.x; Ci0 += a0a.y - a1a.y;
                Cr1 += a0b.x - a1b.x; Ci1 += a0b.y - a1b.y;
                Sr0 += sgn * v64a.x; Si0 += sgn * v64a.y;
                Sr1 += sgn * v64b.x; Si1 += sgn * v64b.y;
            }
        }
        if (f <= 15) {   // j = f : X = C - iS
            *(float4*)&sX[f * 32 + c0] = make_float4(Cr0 + Si0, Ci0 - Sr0, Cr1 + Si1, Ci1 - Sr1);
        }
        {                // j = 32 - f : X = C + iS
            *(float4*)&sX[(32 - f) * 32 + c0] = make_float4(Cr0 - Si0, Ci0 + Sr0, Cr1 - Si1, Ci1 + Sr1);
        }
    }
    // j = 0 reduction (all threads contribute partials)
    {
        int c = tid & 31, grp = tid >> 5;    // 8 groups x 8 h
        float2 acc = make_float2(0.f, 0.f);
#pragma unroll
        for (int h = grp * 8; h < grp * 8 + 8; h++) {
            float2 u = sUE[h * 32 + c];
            acc.x += u.x; acc.y += u.y;
        }
        sRd[grp * 32 + c] = acc;
    }
    __syncthreads();
    if (tid < 32) {
        float2 s = sUO[tid];                 // a128
        float2 u64 = sVE[tid];
        s.x += u64.x; s.y += u64.y;
#pragma unroll
        for (int g = 0; g < 8; g++) { s.x += sRd[g * 32 + tid].x; s.y += sRd[g * 32 + tid].y; }
        sX[tid] = s;
    }
    __syncthreads();
    // -------- phase B mix: thread = (j, 4 co) --------
    {
        int jq = tid >> 3, coq = (tid & 7) * 4;
        const float4* wrow = (const float4*)(g_Wt + ((size_t)(jq * EM1 + kw)) * 1024 + coq);
        const float2* xrow = sX + jq * 32;
        float r0 = 0.f, i0 = 0.f, r1 = 0.f, i1 = 0.f;
        float r2 = 0.f, i2 = 0.f, r3 = 0.f, i3 = 0.f;
#pragma unroll 8
        for (int ci = 0; ci < 32; ci++) {
            float4 w0 = __ldg(&wrow[ci * 16]);
            float4 w1 = __ldg(&wrow[ci * 16 + 1]);
            float2 xv = xrow[ci];
            r0 += xv.x * w0.x - xv.y * w0.y;  i0 += xv.x * w0.y + xv.y * w0.x;
            r1 += xv.x * w0.z - xv.y * w0.w;  i1 += xv.x * w0.w + xv.y * w0.z;
            r2 += xv.x * w1.x - xv.y * w1.y;  i2 += xv.x * w1.y + xv.y * w1.x;
            r3 += xv.x * w1.z - xv.y * w1.w;  i3 += xv.x * w1.w + xv.y * w1.z;
        }
        *(float4*)&sY[jq * 32 + coq]     = make_float4(r0, i0, r1, i1);
        *(float4*)&sY[jq * 32 + coq + 2] = make_float4(r2, i2, r3, i3);
    }
    __syncthreads();
    // -------- phase C fold Y -> P/Q --------
    for (int i = tid; i < EM1 * 32; i += 256) {
        int f = i >> 5, c = i & 31;
        float2 p, q;
        if (f == 0) { p = sY[c]; q = make_float2(0.f, 0.f); }
        else if (f == 16) {
            float2 yb = sY[16 * 32 + c];
            p = yb; q = make_float2(-yb.x, -yb.y);
        } else {
            float2 ya = sY[f * 32 + c], yb = sY[(32 - f) * 32 + c];
            p = make_float2(ya.x + yb.x, ya.y + yb.y);
            q = make_float2(ya.x - yb.x, ya.y - yb.y);
        }
        sP[i] = p; sQ[i] = q;
    }
    __syncthreads();
    // -------- phase C hinv: thread = (hg 0..31, 4 ch of 32) --------
    int cig = tid & 7, hg = tid >> 3;
    int c0 = cig * 4;
    float EcR[2][4], EcI[2][4], OcR[2][4], OcI[2][4];
    float EsR[2][4], EsI[2][4], OsR[2][4], OsI[2][4];
    int hx[2];
#pragma unroll
    for (int m = 0; m < 2; m++) {
        hx[m] = 1 + hg + 32 * m;
#pragma unroll
        for (int c = 0; c < 4; c++) {
            EcR[m][c]=0; EcI[m][c]=0; OcR[m][c]=0; OcI[m][c]=0;
            EsR[m][c]=0; EsI[m][c]=0; OsR[m][c]=0; OsI[m][c]=0;
        }
    }
    int ti0 = 0, ti1 = 0;
#pragma unroll
    for (int f = 0; f < 17; f++) {
        float4 p01 = *(const float4*)&sP[f * 32 + c0];
        float4 p23 = *(const float4*)&sP[f * 32 + c0 + 2];
        float4 q01 = *(const float4*)&sQ[f * 32 + c0];
        float4 q23 = *(const float4*)&sQ[f * 32 + c0 + 2];
        float2 t0 = sT[ti0]; ti0 = (ti0 + hx[0]) & 255;
        float2 t1 = sT[ti1]; ti1 = (ti1 + hx[1]) & 255;
        if ((f & 1) == 0) {
            EcR[0][0] += p01.x*t0.x; EcI[0][0] += p01.y*t0.x; EsR[0][0] += q01.x*t0.y; EsI[0][0] += q01.y*t0.y;
            EcR[0][1] += p01.z*t0.x; EcI[0][1] += p01.w*t0.x; EsR[0][1] += q01.z*t0.y; EsI[0][1] += q01.w*t0.y;
            EcR[0][2] += p23.x*t0.x; EcI[0][2] += p23.y*t0.x; EsR[0][2] += q23.x*t0.y; EsI[0][2] += q23.y*t0.y;
            EcR[0][3] += p23.z*t0.x; EcI[0][3] += p23.w*t0.x; EsR[0][3] += q23.z*t0.y; EsI[0][3] += q23.w*t0.y;
            EcR[1][0] += p01.x*t1.x; EcI[1][0] += p01.y*t1.x; EsR[1][0] += q01.x*t1.y; EsI[1][0] += q01.y*t1.y;
            EcR[1][1] += p01.z*t1.x; EcI[1][1] += p01.w*t1.x; EsR[1][1] += q01.z*t1.y; EsI[1][1] += q01.w*t1.y;
            EcR[1][2] += p23.x*t1.x; EcI[1][2] += p23.y*t1.x; EsR[1][2] += q23.x*t1.y; EsI[1][2] += q23.y*t1.y;
            EcR[1][3] += p23.z*t1.x; EcI[1][3] += p23.w*t1.x; EsR[1][3] += q23.z*t1.y; EsI[1][3] += q23.w*t1.y;
        } else {
            OcR[0][0] += p01.x*t0.x; OcI[0][0] += p01.y*t0.x; OsR[0][0] += q01.x*t0.y; OsI[0][0] += q01.y*t0.y;
            OcR[0][1] += p01.z*t0.x; OcI[0][1] += p01.w*t0.x; OsR[0][1] += q01.z*t0.y; OsI[0][1] += q01.w*t0.y;
            OcR[0][2] += p23.x*t0.x; OcI[0][2] += p23.y*t0.x; OsR[0][2] += q23.x*t0.y; OsI[0][2] += q23.y*t0.y;
            OcR[0][3] += p23.z*t0.x; OcI[0][3] += p23.w*t0.x; OsR[0][3] += q23.z*t0.y; OsI[0][3] += q23.w*t0.y;
            OcR[1][0] += p01.x*t1.x; OcI[1][0] += p01.y*t1.x; OsR[1][0] += q01.x*t1.y; OsI[1][0] += q01.y*t1.y;
            OcR[1][1] += p01.z*t1.x; OcI[1][1] += p01.w*t1.x; OsR[1][1] += q01.z*t1.y; OsI[1][1] += q01.w*t1.y;
            OcR[1][2] += p23.x*t1.x; OcI[1][2] += p23.y*t1.x; OsR[1][2] += q23.x*t1.y; OsI[1][2] += q23.y*t1.y;
            OcR[1][3] += p23.z*t1.x; OcI[1][3] += p23.w*t1.x; OsR[1][3] += q23.z*t1.y; OsI[1][3] += q23.w*t1.y;
        }
    }
#pragma unroll
    for (int m = 0; m < 2; m++) {
        int h = hx[m];
        float E1r[4], E1i[4], O1r[4], O1i[4], E2r[4], E2i[4], O2r[4], O2i[4];
#pragma unroll
        for (int c = 0; c < 4; c++) {
            E1r[c] = EcR[m][c] + OcR[m][c]; E1i[c] = EcI[m][c] + OcI[m][c];
            O1r[c] = EsR[m][c] + OsR[m][c]; O1i[c] = EsI[m][c] + OsI[m][c];
            E2r[c] = EcR[m][c] - OcR[m][c]; E2i[c] = EcI[m][c] - OcI[m][c];
            O2r[c] = -EsR[m][c] + OsR[m][c]; O2i[c] = -EsI[m][c] + OsI[m][c];
        }
        {
            int row = b * 256 + h;
            float4* d = (float4*)(g_Z + ((size_t)row * EM1 + kw) * CC + c0);
            d[0] = make_float4(E1r[0]-O1i[0], E1i[0]+O1r[0], E1r[1]-O1i[1], E1i[1]+O1r[1]);
            d[1] = make_float4(E1r[2]-O1i[2], E1i[2]+O1r[2], E1r[3]-O1i[3], E1i[3]+O1r[3]);
            int row2 = b * 256 + (256 - h);
            float4* d2 = (float4*)(g_Z + ((size_t)row2 * EM1 + kw) * CC + c0);
            d2[0] = make_float4(E1r[0]+O1i[0], E1i[0]-O1r[0], E1r[1]+O1i[1], E1i[1]-O1r[1]);
            d2[1] = make_float4(E1r[2]+O1i[2], E1i[2]-O1r[2], E1r[3]+O1i[3], E1i[3]-O1r[3]);
        }
        if (h != 64) {
            int row = b * 256 + (128 - h);
            float4* d = (float4*)(g_Z + ((size_t)row * EM1 + kw) * CC + c0);
            d[0] = make_float4(E2r[0]-O2i[0], E2i[0]+O2r[0], E2r[1]-O2i[1], E2i[1]+O2r[1]);
            d[1] = make_float4(E2r[2]-O2i[2], E2i[2]+O2r[2], E2r[3]-O2i[3], E2i[3]+O2r[3]);
            int row2 = b * 256 + (128 + h);
            float4* d2 = (float4*)(g_Z + ((size_t)row2 * EM1 + kw) * CC + c0);
            d2[0] = make_float4(E2r[0]+O2i[0], E2i[0]-O2r[0], E2r[1]+O2i[1], E2i[1]-O2r[1]);
            d2[1] = make_float4(E2r[2]+O2i[2], E2i[2]-O2r[2], E2r[3]+O2i[3], E2i[3]-O2r[3]);
        }
    }
    // h = 0 and h = 128
    if (tid < 64) {
        int c = tid & 31;
        bool is128 = tid >= 32;
        float2 acc = make_float2(0.f, 0.f);
#pragma unroll
        for (int f = 0; f < 17; f++) {
            float2 p = sP[f * 32 + c];
            float s = (is128 && (f & 1)) ? -1.0f : 1.0f;
            acc.x += s * p.x; acc.y += s * p.y;
        }
        int row = b * 256 + (is128 ? 128 : 0);
        g_Z[((size_t)row * EM1 + kw) * CC + c] = acc;
    }
}

// ---------------- K5: W-inverse (parity fold, twiddle recurrence) + bias ----------------
__global__ void __launch_bounds__(128) k5_winv(const float* __restrict__ bias,
                                               float* __restrict__ out) {
    __shared__ __align__(16) float2 sZ[EM1 * 32];
    __shared__ float sB[32];
    int row = blockIdx.x;
    int tid = threadIdx.x;
    const float4* src = (const float4*)(g_Z + (size_t)row * EM1 * CC);
    float4* sZ4 = (float4*)sZ;
    for (int i = tid; i < 272; i += 128) sZ4[i] = __ldcs(&src[i]);
    if (tid < 32) sB[tid] = bias[tid];
    __syncthreads();
    int cig = tid & 7, wg = tid >> 3;     // wg 0..15
    int c0 = cig * 4;
    float base[4];
#pragma unroll
    for (int c = 0; c < 4; c++) base[c] = sZ[c0 + c].x + sB[c0 + c];
    float* orow = out + (size_t)row * 8192;
    float Pe[4][4], Po[4][4], Qe[4][4], Qo[4][4];
    int wv[4];
    float tr[4], ti_[4], sr[4], si[4];
#pragma unroll
    for (int m = 0; m < 4; m++) {
        wv[m] = 1 + wg + 16 * m;          // 1..64
        float s_, c_;
        sincospif((float)wv[m] / 128.0f, &s_, &c_);
        sr[m] = c_; si[m] = s_;
        tr[m] = c_; ti_[m] = s_;
#pragma unroll
        for (int c = 0; c < 4; c++) { Pe[m][c]=0; Po[m][c]=0; Qe[m][c]=0; Qo[m][c]=0; }
    }
#pragma unroll
    for (int k = 1; k <= 16; k++) {
        float4 z01 = *(const float4*)&sZ[k * 32 + c0];
        float4 z23 = *(const float4*)&sZ[k * 32 + c0 + 2];
#pragma unroll
        for (int m = 0; m < 4; m++) {
            float tx = tr[m], ty = ti_[m];
            tr[m] = tx * sr[m] - ty * si[m];
            ti_[m] = tx * si[m] + ty * sr[m];
            if ((k & 1) == 0) {
                Pe[m][0] += z01.x * tx; Qe[m][0] += z01.y * ty;
                Pe[m][1] += z01.z * tx; Qe[m][1] += z01.w * ty;
                Pe[m][2] += z23.x * tx; Qe[m][2] += z23.y * ty;
                Pe[m][3] += z23.z * tx; Qe[m][3] += z23.w * ty;
            } else {
                Po[m][0] += z01.x * tx; Qo[m][0] += z01.y * ty;
                Po[m][1] += z01.z * tx; Qo[m][1] += z01.w * ty;
                Po[m][2] += z23.x * tx; Qo[m][2] += z23.y * ty;
                Po[m][3] += z23.z * tx; Qo[m][3] += z23.w * ty;
            }
        }
    }
#pragma unroll
    for (int m = 0; m < 4; m++) {
        int w = wv[m];
        float4 o1, o2;
        o1 = make_float4(base[0] + 2.0f*(Pe[m][0]+Po[m][0]-Qe[m][0]-Qo[m][0]),
                         base[1] + 2.0f*(Pe[m][1]+Po[m][1]-Qe[m][1]-Qo[m][1]),
                         base[2] + 2.0f*(Pe[m][2]+Po[m][2]-Qe[m][2]-Qo[m][2]),
                         base[3] + 2.0f*(Pe[m][3]+Po[m][3]-Qe[m][3]-Qo[m][3]));
        o2 = make_float4(base[0] + 2.0f*(Pe[m][0]+Po[m][0]+Qe[m][0]+Qo[m][0]),
                         base[1] + 2.0f*(Pe[m][1]+Po[m][1]+Qe[m][1]+Qo[m][1]),
                         base[2] + 2.0f*(Pe[m][2]+Po[m][2]+Qe[m][2]+Qo[m][2]),
                         base[3] + 2.0f*(Pe[m][3]+Po[m][3]+Qe[m][3]+Qo[m][3]));
        __stcs((float4*)(orow + w * 32 + c0), o1);
        __stcs((float4*)(orow + (256 - w) * 32 + c0), o2);
        if (w != 64) {
            float4 o3, o4;
            o3 = make_float4(base[0] + 2.0f*(Pe[m][0]-Po[m][0]+Qe[m][0]-Qo[m][0]),
                             base[1] + 2.0f*(Pe[m][1]-Po[m][1]+Qe[m][1]-Qo[m][1]),
                             base[2] + 2.0f*(Pe[m][2]-Po[m][2]+Qe[m][2]-Qo[m][2]),
                             base[3] + 2.0f*(Pe[m][3]-Po[m][3]+Qe[m][3]-Qo[m][3]));
            o4 = make_float4(base[0] + 2.0f*(Pe[m][0]-Po[m][0]-Qe[m][0]+Qo[m][0]),
                             base[1] + 2.0f*(Pe[m][1]-Po[m][1]-Qe[m][1]+Qo[m][1]),
                             base[2] + 2.0f*(Pe[m][2]-Po[m][2]-Qe[m][2]+Qo[m][2]),
                             base[3] + 2.0f*(Pe[m][3]-Po[m][3]-Qe[m][3]+Qo[m][3]));
            __stcs((float4*)(orow + (128 - w) * 32 + c0), o3);
            __stcs((float4*)(orow + (128 + w) * 32 + c0), o4);
        }
    }
    // w = 0 and w = 128
    if (tid < 64) {
        int c = tid & 31;
        bool is128 = tid >= 32;
        float acc = 0.f;
#pragma unroll
        for (int k = 1; k <= 16; k++) {
            float zr = sZ[k * 32 + c].x;
            acc += (is128 && (k & 1)) ? -zr : zr;
        }
        __stcs(&orow[(is128 ? 128 * 32 : 0) + c], sZ[c].x + sB[c] + 2.0f * acc);
    }
}

extern "C" void kernel_launch(void* const* d_in, const int* in_sizes, int n_in,
                              void* d_out, int out_size) {
    const float* x    = (const float*)d_in[0];
    const float* w1r  = (const float*)d_in[1];
    const float* w1i  = (const float*)d_in[2];
    const float* w2r  = (const float*)d_in[3];
    const float* w2i  = (const float*)d_in[4];
    const float* bias = (const float*)d_in[5];
    float* out = (float*)d_out;

    size_t smem234 = (size_t)11840 * sizeof(float2);   // 94720 B
    cudaFuncSetAttribute(k234, cudaFuncAttributeMaxDynamicSharedMemorySize,
                         (int)smem234);

    k1_wdft<<<BB * HH + 1088, 128>>>(x, w1r, w1i, w2r, w2i);
    k234<<<BB * EM1, 256, smem234>>>();
    k5_winv<<<BB * HH, 128>>>(bias, out);
}